// round 4
// baseline (speedup 1.0000x reference)
#include <cuda_runtime.h>

// Problem constants (fixed by the dataset shapes)
#define BATCH  4
#define NPTS   16384
#define HALF   8192
#define FDIM   32
#define PSPLIT 16         // point-dimension split (grid balance: 1024 CTAs)
#define CHUNK  512        // HALF / PSPLIT
#define TPB    256
#define QPT    2          // queries per thread in the knn kernel

// Output layout (float32 elements), matching the reference tuple order:
// valid_pc (4,8192,3) | valid_feats (4,8192,32) | n_idx (4,8192) | rnds (1,16384)
#define O_PC    0
#define O_FEATS (BATCH * HALF * 3)                  // 98304
#define O_NIDX  (O_FEATS + BATCH * HALF * FDIM)     // 1146880
#define O_RNDS  (O_NIDX + BATCH * HALF)             // 1179648

// Scratch (static __device__ globals; no runtime allocation)
__device__ float4 g_valid[BATCH][HALF];         // (x, y, z, p2)
__device__ float4 g_query[BATCH][HALF];         // (x, y, z, q2)
__device__ float4 g_part[BATCH][PSPLIT][HALF];  // (d0, d1, bits(i0), bits(i1))

// ---------------------------------------------------------------------------
// Kernel 1: gathers + scratch build.
// Thread space = BATCH*HALF*8 = 262144 (feats float4 lanes); subsets handle
// pc/scratch (BATCH*HALF) and rnds copy (NPTS).
// ---------------------------------------------------------------------------
__global__ __launch_bounds__(TPB) void gather_kernel(
    const float* __restrict__ pc,
    const float* __restrict__ feats,
    const int*   __restrict__ rnds,
    float*       __restrict__ out)
{
    int tid = blockIdx.x * TPB + threadIdx.x;

    // --- feats gather: 32 floats/row = 8 float4 per (b, i) ---
    {
        int b = tid >> 16;            // tid / (HALF*8)
        int r = tid & 0xFFFF;
        int i = r >> 3;
        int v = r & 7;
        int vi = rnds[i];
        float4 f = reinterpret_cast<const float4*>(feats)[(b * NPTS + vi) * 8 + v];
        reinterpret_cast<float4*>(out + O_FEATS)[(b * HALF + i) * 8 + v] = f;
    }

    // --- pc gather + scratch (valid points and queries) ---
    if (tid < BATCH * HALF) {
        int b = tid / HALF;
        int i = tid - b * HALF;

        int vi = rnds[i];
        float x = pc[(b * NPTS + vi) * 3 + 0];
        float y = pc[(b * NPTS + vi) * 3 + 1];
        float z = pc[(b * NPTS + vi) * 3 + 2];
        out[(b * HALF + i) * 3 + 0] = x;
        out[(b * HALF + i) * 3 + 1] = y;
        out[(b * HALF + i) * 3 + 2] = z;
        // p2 exactly like jnp.sum(p*p, -1): ((x*x + y*y) + z*z), each op rounded
        float p2 = __fadd_rn(__fadd_rn(__fmul_rn(x, x), __fmul_rn(y, y)), __fmul_rn(z, z));
        g_valid[b][i] = make_float4(x, y, z, p2);

        int qi = rnds[HALF + i];
        float qx = pc[(b * NPTS + qi) * 3 + 0];
        float qy = pc[(b * NPTS + qi) * 3 + 1];
        float qz = pc[(b * NPTS + qi) * 3 + 2];
        float q2 = __fadd_rn(__fadd_rn(__fmul_rn(qx, qx), __fmul_rn(qy, qy)), __fmul_rn(qz, qz));
        g_query[b][i] = make_float4(qx, qy, qz, q2);
    }

    // --- rnds passthrough (as float) ---
    if (tid < NPTS) {
        out[O_RNDS + tid] = (float)rnds[tid];
    }
}

// ---------------------------------------------------------------------------
// Distance matching the XLA:CPU (Eigen) lowering of the reference:
//   t  = fma(qz,pz, fma(qy,py, rn(qx*px)))   ascending-k fma accumulation
//   d2 = rn( rn(q2 + p2) - (t + t) )         elementwise HLOs each rounded;
//                                            t+t exact (== 2.0*t)
// ---------------------------------------------------------------------------
__device__ __forceinline__ float dist2(float4 Q, float4 p)
{
    float t = __fmaf_rn(Q.z, p.z, __fmaf_rn(Q.y, p.y, __fmul_rn(Q.x, p.x)));
    return __fadd_rn(__fadd_rn(Q.w, p.w), -__fadd_rn(t, t));
}

// Branchless top-2 update; strict '<' with ascending-index scan reproduces
// lax.top_k tie-breaking (lowest index wins on exact ties).
__device__ __forceinline__ void top2_update(float d, int j,
                                            float& d0, float& d1, int& i0, int& i1)
{
    bool lt1 = d < d1;
    bool lt0 = d < d0;
    d1 = lt0 ? d0 : (lt1 ? d : d1);
    i1 = lt0 ? i0 : (lt1 ? j : i1);
    d0 = lt0 ? d  : d0;
    i0 = lt0 ? j  : i0;
}

// ---------------------------------------------------------------------------
// Kernel 2: brute-force top-2 over one point chunk per CTA, 2 queries/thread.
// Grid = 16 x 16 x 4 = 1024 CTAs (fully resident single wave on 148 SMs).
// ---------------------------------------------------------------------------
__global__ __launch_bounds__(TPB) void knn_kernel()
{
    __shared__ float4 sp[CHUNK];

    int b = blockIdx.z;
    int c = blockIdx.y;
    int base = c * CHUNK;

    #pragma unroll
    for (int j = threadIdx.x; j < CHUNK; j += TPB)
        sp[j] = g_valid[b][base + j];
    __syncthreads();

    int qa = blockIdx.x * (TPB * QPT) + threadIdx.x;   // query 0
    int qb = qa + TPB;                                 // query 1
    float4 Qa = g_query[b][qa];
    float4 Qb = g_query[b][qb];

    float a0 = 3.0e38f, a1 = 3.0e38f;  int ai0 = 0, ai1 = 0;
    float b0 = 3.0e38f, b1 = 3.0e38f;  int bi0 = 0, bi1 = 0;

    #pragma unroll 16
    for (int j = 0; j < CHUNK; j++) {
        float4 p = sp[j];
        float da = dist2(Qa, p);
        float db = dist2(Qb, p);
        top2_update(da, base + j, a0, a1, ai0, ai1);
        top2_update(db, base + j, b0, b1, bi0, bi1);
    }

    g_part[b][c][qa] = make_float4(a0, a1, __int_as_float(ai0), __int_as_float(ai1));
    g_part[b][c][qb] = make_float4(b0, b1, __int_as_float(bi0), __int_as_float(bi1));
}

// ---------------------------------------------------------------------------
// Kernel 3: merge PSPLIT partial top-2 lists (ascending chunk order keeps the
// lowest-index-wins tie semantics), emit 2nd-nearest index as float.
// ---------------------------------------------------------------------------
__global__ __launch_bounds__(TPB) void merge_kernel(float* __restrict__ out)
{
    int tid = blockIdx.x * TPB + threadIdx.x;
    if (tid >= BATCH * HALF) return;
    int b = tid / HALF;
    int q = tid - b * HALF;

    float d0 = 3.0e38f, d1 = 3.0e38f;
    int i0 = 0, i1 = 0;

    #pragma unroll
    for (int c = 0; c < PSPLIT; c++) {
        float4 p = g_part[b][c][q];
        top2_update(p.x, __float_as_int(p.z), d0, d1, i0, i1);
        top2_update(p.y, __float_as_int(p.w), d0, d1, i0, i1);
    }

    out[O_NIDX + tid] = (float)i1;
}

// ---------------------------------------------------------------------------
extern "C" void kernel_launch(void* const* d_in, const int* in_sizes, int n_in,
                              void* d_out, int out_size)
{
    const float* pc    = (const float*)d_in[0];
    const float* feats = (const float*)d_in[1];
    const int*   rnds  = (const int*)  d_in[2];
    float* out = (float*)d_out;

    gather_kernel<<<(BATCH * HALF * 8) / TPB, TPB>>>(pc, feats, rnds, out);
    knn_kernel<<<dim3(HALF / (TPB * QPT), PSPLIT, BATCH), TPB>>>();
    merge_kernel<<<(BATCH * HALF + TPB - 1) / TPB, TPB>>>(out);
}

// round 5
// speedup vs baseline: 1.0405x; 1.0405x over previous
#include <cuda_runtime.h>

// Problem constants (fixed by the dataset shapes)
#define BATCH  4
#define NPTS   16384
#define HALF   8192
#define FDIM   32

// knn kernel geometry: persistent top-2 state over SPAN points per thread.
#define TPB2   64
#define NSPLIT 2                  // point-dim split (2 spans of 4096)
#define SPAN   (HALF / NSPLIT)    // 4096
#define STAGE  512                // smem staging granularity
#define NSTAGE (SPAN / STAGE)     // 8
#define PRE    (STAGE / TPB2)     // 8 float4 prefetch regs per thread

#define TPB    256                // gather/merge blocks

// Output layout (float32 elements), matching the reference tuple order:
// valid_pc (4,8192,3) | valid_feats (4,8192,32) | n_idx (4,8192) | rnds (1,16384)
#define O_PC    0
#define O_FEATS (BATCH * HALF * 3)                  // 98304
#define O_NIDX  (O_FEATS + BATCH * HALF * FDIM)     // 1146880
#define O_RNDS  (O_NIDX + BATCH * HALF)             // 1179648

// Scratch (static __device__ globals; no runtime allocation)
__device__ float4 g_valid[BATCH][HALF];         // (x, y, z, p2)
__device__ float4 g_query[BATCH][HALF];         // (x, y, z, q2)
__device__ float4 g_part[BATCH][NSPLIT][HALF];  // (d0, d1, bits(i0), bits(i1))

// ---------------------------------------------------------------------------
// Kernel 1: gathers + scratch build (unchanged; 6.6us, latency-bound, 4% of total)
// ---------------------------------------------------------------------------
__global__ __launch_bounds__(TPB) void gather_kernel(
    const float* __restrict__ pc,
    const float* __restrict__ feats,
    const int*   __restrict__ rnds,
    float*       __restrict__ out)
{
    int tid = blockIdx.x * TPB + threadIdx.x;

    // --- feats gather: 32 floats/row = 8 float4 per (b, i) ---
    {
        int b = tid >> 16;            // tid / (HALF*8)
        int r = tid & 0xFFFF;
        int i = r >> 3;
        int v = r & 7;
        int vi = rnds[i];
        float4 f = reinterpret_cast<const float4*>(feats)[(b * NPTS + vi) * 8 + v];
        reinterpret_cast<float4*>(out + O_FEATS)[(b * HALF + i) * 8 + v] = f;
    }

    // --- pc gather + scratch (valid points and queries) ---
    if (tid < BATCH * HALF) {
        int b = tid / HALF;
        int i = tid - b * HALF;

        int vi = rnds[i];
        float x = pc[(b * NPTS + vi) * 3 + 0];
        float y = pc[(b * NPTS + vi) * 3 + 1];
        float z = pc[(b * NPTS + vi) * 3 + 2];
        out[(b * HALF + i) * 3 + 0] = x;
        out[(b * HALF + i) * 3 + 1] = y;
        out[(b * HALF + i) * 3 + 2] = z;
        // p2 exactly like jnp.sum(p*p, -1): ((x*x + y*y) + z*z), each op rounded
        float p2 = __fadd_rn(__fadd_rn(__fmul_rn(x, x), __fmul_rn(y, y)), __fmul_rn(z, z));
        g_valid[b][i] = make_float4(x, y, z, p2);

        int qi = rnds[HALF + i];
        float qx = pc[(b * NPTS + qi) * 3 + 0];
        float qy = pc[(b * NPTS + qi) * 3 + 1];
        float qz = pc[(b * NPTS + qi) * 3 + 2];
        float q2 = __fadd_rn(__fadd_rn(__fmul_rn(qx, qx), __fmul_rn(qy, qy)), __fmul_rn(qz, qz));
        g_query[b][i] = make_float4(qx, qy, qz, q2);
    }

    // --- rnds passthrough (as float) ---
    if (tid < NPTS) {
        out[O_RNDS + tid] = (float)rnds[tid];
    }
}

// ---------------------------------------------------------------------------
// Distance: verified bit-exact vs reference (rel_err == 0.0 in round 4).
//   t  = fma(qz,pz, fma(qy,py, rn(qx*px)))
//   d2 = rn( rn(q2 + p2) - (t + t) )
// DO NOT reorder/refuse these ops.
// ---------------------------------------------------------------------------
__device__ __forceinline__ float dist2(float4 Q, float4 p)
{
    float t = __fmaf_rn(Q.z, p.z, __fmaf_rn(Q.y, p.y, __fmul_rn(Q.x, p.x)));
    return __fadd_rn(__fadd_rn(Q.w, p.w), -__fadd_rn(t, t));
}

// ---------------------------------------------------------------------------
// Kernel 2: persistent-state brute-force top-2.
// 1024 CTAs x 64 threads; each thread owns ONE query and scans SPAN=4096
// points in ascending order (smem-staged, register-prefetched). Top-2 state
// persists across the whole span -> update branch taken ~8% of iterations,
// so the hot path is 1 LDS + 6 float + 1 FSETP + branch (fma-pipe bound).
// Strict '<' + ascending index scan == lax.top_k tie-break (lowest index).
// ---------------------------------------------------------------------------
__global__ __launch_bounds__(TPB2) void knn_kernel()
{
    __shared__ float4 sp[STAGE];

    int b = blockIdx.z;
    int c = blockIdx.y;               // span index: 0..NSPLIT-1
    int base = c * SPAN;

    int q = blockIdx.x * TPB2 + threadIdx.x;
    float4 Q = g_query[b][q];

    // preload stage 0
    #pragma unroll
    for (int t = 0; t < PRE; t++)
        sp[t * TPB2 + threadIdx.x] = g_valid[b][base + t * TPB2 + threadIdx.x];
    __syncthreads();

    float d0 = 3.0e38f, d1 = 3.0e38f;
    int i0 = 0, i1 = 0;

    for (int s = 0; s < NSTAGE; s++) {
        // prefetch next stage into registers (overlaps with compute below)
        float4 pre[PRE];
        if (s + 1 < NSTAGE) {
            #pragma unroll
            for (int t = 0; t < PRE; t++)
                pre[t] = g_valid[b][base + (s + 1) * STAGE + t * TPB2 + threadIdx.x];
        }

        int pbase = base + s * STAGE;
        #pragma unroll 8
        for (int j = 0; j < STAGE; j++) {
            float4 p = sp[j];
            float d2 = dist2(Q, p);
            if (d2 < d1) {                       // rare (~8% warp-taken)
                bool lt0 = d2 < d0;
                d1 = lt0 ? d0 : d2;  i1 = lt0 ? i0 : (pbase + j);
                d0 = lt0 ? d2 : d0;  i0 = lt0 ? (pbase + j) : i0;
            }
        }

        if (s + 1 < NSTAGE) {
            __syncthreads();                     // everyone done reading sp
            #pragma unroll
            for (int t = 0; t < PRE; t++)
                sp[t * TPB2 + threadIdx.x] = pre[t];
            __syncthreads();                     // sp refilled
        }
    }

    g_part[b][c][q] = make_float4(d0, d1, __int_as_float(i0), __int_as_float(i1));
}

// ---------------------------------------------------------------------------
// Kernel 3: merge NSPLIT partial top-2 lists (ascending span order keeps the
// lowest-index-wins tie semantics), emit 2nd-nearest index as float.
// ---------------------------------------------------------------------------
__device__ __forceinline__ void top2_update(float d, int j,
                                            float& d0, float& d1, int& i0, int& i1)
{
    bool lt1 = d < d1;
    bool lt0 = d < d0;
    d1 = lt0 ? d0 : (lt1 ? d : d1);
    i1 = lt0 ? i0 : (lt1 ? j : i1);
    d0 = lt0 ? d  : d0;
    i0 = lt0 ? j  : i0;
}

__global__ __launch_bounds__(TPB) void merge_kernel(float* __restrict__ out)
{
    int tid = blockIdx.x * TPB + threadIdx.x;
    if (tid >= BATCH * HALF) return;
    int b = tid / HALF;
    int q = tid - b * HALF;

    float d0 = 3.0e38f, d1 = 3.0e38f;
    int i0 = 0, i1 = 0;

    #pragma unroll
    for (int c = 0; c < NSPLIT; c++) {
        float4 p = g_part[b][c][q];
        top2_update(p.x, __float_as_int(p.z), d0, d1, i0, i1);
        top2_update(p.y, __float_as_int(p.w), d0, d1, i0, i1);
    }

    out[O_NIDX + tid] = (float)i1;
}

// ---------------------------------------------------------------------------
extern "C" void kernel_launch(void* const* d_in, const int* in_sizes, int n_in,
                              void* d_out, int out_size)
{
    const float* pc    = (const float*)d_in[0];
    const float* feats = (const float*)d_in[1];
    const int*   rnds  = (const int*)  d_in[2];
    float* out = (float*)d_out;

    gather_kernel<<<(BATCH * HALF * 8) / TPB, TPB>>>(pc, feats, rnds, out);
    knn_kernel<<<dim3(HALF / TPB2, NSPLIT, BATCH), TPB2>>>();
    merge_kernel<<<(BATCH * HALF + TPB - 1) / TPB, TPB>>>(out);
}

// round 11
// speedup vs baseline: 1.2711x; 1.2216x over previous
#include <cuda_runtime.h>

// Problem constants (fixed by the dataset shapes)
#define BATCH  4
#define NPTS   16384
#define HALF   8192
#define FDIM   32

// knn kernel geometry: persistent top-2 state over SPAN points per thread.
#define TPB2   64
#define NSPLIT 2                  // point-dim split (2 spans of 4096)
#define SPAN   (HALF / NSPLIT)    // 4096
#define STAGE  512                // smem staging granularity
#define NSTAGE (SPAN / STAGE)     // 8
#define PRE    (STAGE / TPB2)     // 8 float4 prefetch regs per thread

#define TPB    256                // gather/merge blocks

// Conservative filter slack (absolute, on d2 scale). Worst-case rounding
// discrepancy between the fused filter h+q2 and the exact-chain d2 is
// <= ~4e-5 for this data (coords ~N(0,1), intermediates <= ~80). 1e-3 is a
// 25x margin; the filter can only ADD candidates, never drop a true update.
#define EPS 1.0e-3f

// Output layout (float32 elements), matching the reference tuple order:
// valid_pc (4,8192,3) | valid_feats (4,8192,32) | n_idx (4,8192) | rnds (1,16384)
#define O_PC    0
#define O_FEATS (BATCH * HALF * 3)                  // 98304
#define O_NIDX  (O_FEATS + BATCH * HALF * FDIM)     // 1146880
#define O_RNDS  (O_NIDX + BATCH * HALF)             // 1179648

// Scratch (static __device__ globals; no runtime allocation)
__device__ float4 g_valid[BATCH][HALF];         // (x, y, z, p2)
__device__ float4 g_query[BATCH][HALF];         // (x, y, z, q2)
__device__ float4 g_part[BATCH][NSPLIT][HALF];  // (d0, d1, bits(i0), bits(i1))

// ---------------------------------------------------------------------------
// Kernel 1: gathers + scratch build (6.5us, latency-bound, 4% of total)
// ---------------------------------------------------------------------------
__global__ __launch_bounds__(TPB) void gather_kernel(
    const float* __restrict__ pc,
    const float* __restrict__ feats,
    const int*   __restrict__ rnds,
    float*       __restrict__ out)
{
    int tid = blockIdx.x * TPB + threadIdx.x;

    // --- feats gather: 32 floats/row = 8 float4 per (b, i) ---
    {
        int b = tid >> 16;            // tid / (HALF*8)
        int r = tid & 0xFFFF;
        int i = r >> 3;
        int v = r & 7;
        int vi = rnds[i];
        float4 f = reinterpret_cast<const float4*>(feats)[(b * NPTS + vi) * 8 + v];
        reinterpret_cast<float4*>(out + O_FEATS)[(b * HALF + i) * 8 + v] = f;
    }

    // --- pc gather + scratch (valid points and queries) ---
    if (tid < BATCH * HALF) {
        int b = tid / HALF;
        int i = tid - b * HALF;

        int vi = rnds[i];
        float x = pc[(b * NPTS + vi) * 3 + 0];
        float y = pc[(b * NPTS + vi) * 3 + 1];
        float z = pc[(b * NPTS + vi) * 3 + 2];
        out[(b * HALF + i) * 3 + 0] = x;
        out[(b * HALF + i) * 3 + 1] = y;
        out[(b * HALF + i) * 3 + 2] = z;
        // p2 exactly like jnp.sum(p*p, -1): ((x*x + y*y) + z*z), each op rounded
        float p2 = __fadd_rn(__fadd_rn(__fmul_rn(x, x), __fmul_rn(y, y)), __fmul_rn(z, z));
        g_valid[b][i] = make_float4(x, y, z, p2);

        int qi = rnds[HALF + i];
        float qx = pc[(b * NPTS + qi) * 3 + 0];
        float qy = pc[(b * NPTS + qi) * 3 + 1];
        float qz = pc[(b * NPTS + qi) * 3 + 2];
        float q2 = __fadd_rn(__fadd_rn(__fmul_rn(qx, qx), __fmul_rn(qy, qy)), __fmul_rn(qz, qz));
        g_query[b][i] = make_float4(qx, qy, qz, q2);
    }

    // --- rnds passthrough (as float) ---
    if (tid < NPTS) {
        out[O_RNDS + tid] = (float)rnds[tid];
    }
}

// ---------------------------------------------------------------------------
// Distance: verified bit-exact vs reference (rel_err == 0.0, rounds 4+5).
//   t  = fma(qz,pz, fma(qy,py, rn(qx*px)))
//   d2 = rn( rn(q2 + p2) - (t + t) )
// DO NOT reorder/refuse these ops. Only used on filter hits.
// ---------------------------------------------------------------------------
__device__ __forceinline__ float dist2(float4 Q, float4 p)
{
    float t = __fmaf_rn(Q.z, p.z, __fmaf_rn(Q.y, p.y, __fmul_rn(Q.x, p.x)));
    return __fadd_rn(__fadd_rn(Q.w, p.w), -__fadd_rn(t, t));
}

// Exact strict-'<' top-2 update (ascending index order == lax.top_k tie-break).
__device__ __forceinline__ void exact_update(float4 Q, float4 p, int idx,
                                             float& d0, float& d1, int& i0, int& i1,
                                             float& thr)
{
    float d2v = dist2(Q, p);
    if (d2v < d1) {
        bool lt0 = d2v < d0;
        d1 = lt0 ? d0 : d2v;  i1 = lt0 ? i0 : idx;
        d0 = lt0 ? d2v : d0;  i0 = lt0 ? idx : i0;
        thr = (d1 - Q.w) + EPS;
    }
}

// ---------------------------------------------------------------------------
// Kernel 2: persistent-state brute-force top-2 with a 3-FFMA conservative
// filter, PAIRED across 2 points per vote to amortize compare/vote/branch.
// Hot path per 2 points: 2 LDS.128 + 6 FFMA + FMNMX + FSETP + VOTE.
// fmin(ha,hb) < thr  <=>  ha < thr || hb < thr, so the pairing keeps the
// filter conservative. On a warp-any hit (warp-UNIFORM branch -> real BRA,
// not body predication), both points are re-examined with the pinned
// bit-exact dist2 in ascending index order.
// ---------------------------------------------------------------------------
__global__ __launch_bounds__(TPB2) void knn_kernel()
{
    __shared__ float4 sp[STAGE];

    int b = blockIdx.z;
    int c = blockIdx.y;               // span index: 0..NSPLIT-1
    int base = c * SPAN;

    int q = blockIdx.x * TPB2 + threadIdx.x;
    float4 Q = g_query[b][q];

    // Filter coefficients: m = -2*Q (exact scaling by power of two)
    float mx = __fmul_rn(-2.0f, Q.x);
    float my = __fmul_rn(-2.0f, Q.y);
    float mz = __fmul_rn(-2.0f, Q.z);

    // preload stage 0
    #pragma unroll
    for (int t = 0; t < PRE; t++)
        sp[t * TPB2 + threadIdx.x] = g_valid[b][base + t * TPB2 + threadIdx.x];
    __syncthreads();

    float d0 = 3.0e38f, d1 = 3.0e38f;
    int i0 = 0, i1 = 0;
    float thr = 3.0e38f;              // = d1 - q2 + EPS (recomputed on update)

    for (int s = 0; s < NSTAGE; s++) {
        // prefetch next stage into registers (overlaps with compute below)
        float4 pre[PRE];
        if (s + 1 < NSTAGE) {
            #pragma unroll
            for (int t = 0; t < PRE; t++)
                pre[t] = g_valid[b][base + (s + 1) * STAGE + t * TPB2 + threadIdx.x];
        }

        int pbase = base + s * STAGE;
        #pragma unroll 8
        for (int j = 0; j < STAGE; j += 2) {
            float4 pa = sp[j];
            float4 pb = sp[j + 1];
            // h ~= p2 - 2*(q.p): 3 fused FFMA each, conservative vs d2-q2
            float ha = __fmaf_rn(mx, pa.x, __fmaf_rn(my, pa.y, __fmaf_rn(mz, pa.z, pa.w)));
            float hb = __fmaf_rn(mx, pb.x, __fmaf_rn(my, pb.y, __fmaf_rn(mz, pb.z, pb.w)));
            float hmin = fminf(ha, hb);
            if (__any_sync(0xFFFFFFFFu, hmin < thr)) {   // warp-uniform, rare
                exact_update(Q, pa, pbase + j,     d0, d1, i0, i1, thr);
                exact_update(Q, pb, pbase + j + 1, d0, d1, i0, i1, thr);
            }
        }

        if (s + 1 < NSTAGE) {
            __syncthreads();                     // everyone done reading sp
            #pragma unroll
            for (int t = 0; t < PRE; t++)
                sp[t * TPB2 + threadIdx.x] = pre[t];
            __syncthreads();                     // sp refilled
        }
    }

    g_part[b][c][q] = make_float4(d0, d1, __int_as_float(i0), __int_as_float(i1));
}

// ---------------------------------------------------------------------------
// Kernel 3: merge NSPLIT partial top-2 lists (ascending span order keeps the
// lowest-index-wins tie semantics), emit 2nd-nearest index as float.
// ---------------------------------------------------------------------------
__device__ __forceinline__ void top2_update(float d, int j,
                                            float& d0, float& d1, int& i0, int& i1)
{
    bool lt1 = d < d1;
    bool lt0 = d < d0;
    d1 = lt0 ? d0 : (lt1 ? d : d1);
    i1 = lt0 ? i0 : (lt1 ? j : i1);
    d0 = lt0 ? d  : d0;
    i0 = lt0 ? j  : i0;
}

__global__ __launch_bounds__(TPB) void merge_kernel(float* __restrict__ out)
{
    int tid = blockIdx.x * TPB + threadIdx.x;
    if (tid >= BATCH * HALF) return;
    int b = tid / HALF;
    int q = tid - b * HALF;

    float d0 = 3.0e38f, d1 = 3.0e38f;
    int i0 = 0, i1 = 0;

    #pragma unroll
    for (int c = 0; c < NSPLIT; c++) {
        float4 p = g_part[b][c][q];
        top2_update(p.x, __float_as_int(p.z), d0, d1, i0, i1);
        top2_update(p.y, __float_as_int(p.w), d0, d1, i0, i1);
    }

    out[O_NIDX + tid] = (float)i1;
}

// ---------------------------------------------------------------------------
extern "C" void kernel_launch(void* const* d_in, const int* in_sizes, int n_in,
                              void* d_out, int out_size)
{
    const float* pc    = (const float*)d_in[0];
    const float* feats = (const float*)d_in[1];
    const int*   rnds  = (const int*)  d_in[2];
    float* out = (float*)d_out;

    gather_kernel<<<(BATCH * HALF * 8) / TPB, TPB>>>(pc, feats, rnds, out);
    knn_kernel<<<dim3(HALF / TPB2, NSPLIT, BATCH), TPB2>>>();
    merge_kernel<<<(BATCH * HALF + TPB - 1) / TPB, TPB>>>(out);
}